// round 16
// baseline (speedup 1.0000x reference)
#include <cuda_runtime.h>
#include <cuda_bf16.h>

typedef unsigned long long ull;

// Problem shapes (fixed)
#define BN 16
#define FN 4096
#define MN 512
#define DN 256
#define VEN 64
#define HN 512
#define OUTN 8
#define VN 50
#define INW 320          // VEN + DN
#define NSEG 8192        // BN * MN

#define NPB 1024         // proj main blocks: 8192 warps = 4096 chunks x 2 halves
#define FRPW 16          // frames per chunk (contiguous)

// ---------------------------------------------------------------------------
// Scratch (floats).
//   sum   [NSEG*8]  @ 0        cnt [NSEG] @ 65536
//     -> zeroed by final_kernel of the PREVIOUS replay (BSS-zero on 1st call)
//   Wf    [2048]    @ 73728    k-major ull view: ull[k*128+jp] = (Wc[64+2jp][k], Wc[64+2jp+1][k])
//   WcEmb [512]     @ 75776    bc [8] @ 76288    pe [400] @ 76296
//     -> single-writer plain stores each replay (no zeroing needed)
// ---------------------------------------------------------------------------
#define OFF_SUM   0
#define OFF_CNT   65536
#define OFF_WF    73728
#define OFF_WCEMB 75776
#define OFF_BC    76288
#define OFF_PE    76296
#define SCR_TOTAL 76704

__device__ __align__(16) float g_scr[SCR_TOTAL];

__device__ __forceinline__ ull fma2(ull a, ull b, ull c) {
    ull d;
    asm("fma.rn.f32x2 %0, %1, %2, %3;" : "=l"(d) : "l"(a), "l"(b), "l"(c));
    return d;
}
__device__ __forceinline__ ull add2(ull a, ull b) {
    ull d;
    asm("add.rn.f32x2 %0, %1, %2;" : "=l"(d) : "l"(a), "l"(b));
    return d;
}

// ---------------------------------------------------------------------------
// Transposed warp reduction: v[0..7] per lane (k partials) -> each lane
// returns the full warp sum for k = lane & 7. 9 shuffles.
// ---------------------------------------------------------------------------
__device__ __forceinline__ float warp_reduce_k(const float v[8], int lane) {
    const unsigned FULL = 0xFFFFFFFFu;
    float nv[4];
    const int b0 = lane & 1;
#pragma unroll
    for (int i = 0; i < 4; i++) {
        float keep = b0 ? v[2 * i + 1] : v[2 * i];
        float send = b0 ? v[2 * i]     : v[2 * i + 1];
        nv[i] = keep + __shfl_xor_sync(FULL, send, 1);
    }
    const int b1 = (lane >> 1) & 1;
    float mv[2];
#pragma unroll
    for (int i = 0; i < 2; i++) {
        float keep = b1 ? nv[2 * i + 1] : nv[2 * i];
        float send = b1 ? nv[2 * i]     : nv[2 * i + 1];
        mv[i] = keep + __shfl_xor_sync(FULL, send, 2);
    }
    const int b2 = (lane >> 2) & 1;
    float keep = b2 ? mv[1] : mv[0];
    float send = b2 ? mv[0] : mv[1];
    float s = keep + __shfl_xor_sync(FULL, send, 4);
    s += __shfl_xor_sync(FULL, s, 8);
    s += __shfl_xor_sync(FULL, s, 16);
    return s;   // k = lane & 7
}

// ---------------------------------------------------------------------------
// Kernel A: fold Wc = W_mora @ W_post + bc. Warp-per-row (321 warps), full
// H=512 per warp, SINGLE-WRITER plain stores (no atomics, no zeroed slots).
// ---------------------------------------------------------------------------
__global__ __launch_bounds__(256) void fold_kernel(
    const float* __restrict__ W_mora,   // [320, 512]
    const float* __restrict__ b_mora,   // [512]
    const float* __restrict__ W_post,   // [512, 8]
    const float* __restrict__ b_post)   // [8]
{
    const int tid = threadIdx.x;
    const int lane = tid & 31;
    const int i = blockIdx.x * 8 + (tid >> 5);   // row 0..327
    if (i > INW) return;

    const float* src = (i < INW) ? (W_mora + (size_t)i * HN) : b_mora;

    float acc[8];
#pragma unroll
    for (int k = 0; k < 8; k++) acc[k] = 0.0f;

#pragma unroll
    for (int j = 0; j < 16; j++) {
        const int h = 32 * j + lane;
        const float a = src[h];
        const float4* wp = (const float4*)(W_post + h * OUTN);
        float4 p0 = wp[0], p1 = wp[1];
        acc[0] += a * p0.x; acc[1] += a * p0.y; acc[2] += a * p0.z; acc[3] += a * p0.w;
        acc[4] += a * p1.x; acc[5] += a * p1.y; acc[6] += a * p1.z; acc[7] += a * p1.w;
    }

    float s = warp_reduce_k(acc, lane);
    if (lane < 8) {
        const int k = lane;
        if (i < VEN) {
            g_scr[OFF_WCEMB + i * OUTN + k] = s;
        } else if (i < INW) {
            const int j = i - VEN;
            g_scr[OFF_WF + (k * 128 + (j >> 1)) * 2 + (j & 1)] = s;
        } else {
            g_scr[OFF_BC + k] = s + b_post[k];
        }
    }
}

// ---------------------------------------------------------------------------
// Flush (half-frame): project this warp's 4-per-lane run-sum (2 f32x2,
// dims [half*128, half*128+128)) with its half of the smem weights,
// transposed reduce, atomic scatter. cnt added by half 0 only.
// ---------------------------------------------------------------------------
__device__ __noinline__ void flush_half(const ull* __restrict__ sWf,
                                        const ull* __restrict__ racc,
                                        float fcnt, int seg, int lane, int half) {
    const int jp = half * 64 + 2 * lane;
    float v[8];
#pragma unroll
    for (int k = 0; k < 8; k++) {
        ulonglong2 wa = *(const ulonglong2*)(sWf + k * 128 + jp);
        ull t = fma2(racc[0], wa.x, fma2(racc[1], wa.y, 0ull));
        float lo = __int_as_float((int)(t & 0xFFFFFFFFull));
        float hi = __int_as_float((int)(t >> 32));
        v[k] = lo + hi;
    }
    float s = warp_reduce_k(v, lane);
    if (lane < 8) atomicAdd(g_scr + OFF_SUM + seg * OUTN + lane, s);
    else if (lane == 8 && half == 0) atomicAdd(g_scr + OFF_CNT + seg, fcnt);
}

// ---------------------------------------------------------------------------
// Kernel B: warp pair per 16-frame chunk (half 0: dims 0-127, half 1: 128-255).
// 1 LDG.128 per frame per lane; 8-frame batches, 2-deep software pipeline.
// Extra blocks compute pe.  (R15 winner, unchanged.)
// ---------------------------------------------------------------------------
__global__ __launch_bounds__(256) void proj_kernel(
    const float* __restrict__ features,   // [B, F, D]
    const int* __restrict__ mora_index,   // [B, F]
    const float* __restrict__ emb_table)  // [V, VE]
{
    const unsigned FULL = 0xFFFFFFFFu;

    if (blockIdx.x >= NPB) {
        // per-vowel embedding projection: pe[v][k] = emb[v] . WcEmb[:,k]
        const int gt = (blockIdx.x - NPB) * 256 + threadIdx.x;  // 2 blocks >= 400
        if (gt < VN * OUTN) {
            const int v = gt >> 3, k = gt & 7;
            const float* e = emb_table + v * VEN;
            float s = 0.0f;
#pragma unroll 8
            for (int j = 0; j < VEN; j++) s += e[j] * g_scr[OFF_WCEMB + j * OUTN + k];
            g_scr[OFF_PE + gt] = s;
        }
        return;
    }

    __shared__ __align__(16) ull sWf[128 * 8];   // 8 KB, k-major
    const int tid = threadIdx.x;
    for (int j = tid; j < 128 * 8 / 2; j += 256)
        ((ulonglong2*)sWf)[j] = ((const ulonglong2*)(g_scr + OFF_WF))[j];
    __syncthreads();

    const int lane = tid & 31;
    const int gw = (blockIdx.x * 256 + tid) >> 5;   // 0..8191
    const int chunk = gw >> 1;                      // 0..4095
    const int half = gw & 1;                        // dim half
    const int base = chunk * FRPW;                  // 16 contiguous frames
    const int b = base >> 12;                       // / FN

    // preload the 16 mora indices for this chunk (one coalesced LDG)
    const int myidx = mora_index[base + (lane & 15)];

    ull racc[2];
    racc[0] = racc[1] = 0ull;
    float fcnt = 0.0f;
    int curm = __shfl_sync(FULL, myidx, 0);

    // lane covers dims [half*128 + 4*lane, +4): one ulonglong2 per frame
    const ulonglong2* fr =
        (const ulonglong2*)(features + (size_t)base * DN + half * 128);

    // 2-deep software pipeline over 2 batches of 8 frames
    ulonglong2 x[2][8];
#pragma unroll
    for (int j = 0; j < 8; j++) x[0][j] = fr[j * 64 + lane];

#pragma unroll
    for (int bt = 0; bt < 2; bt++) {
        if (bt == 0) {
            // issue batch 1's 8 LDG.128 before consuming batch 0
#pragma unroll
            for (int j = 0; j < 8; j++) x[1][j] = fr[(8 + j) * 64 + lane];
        }
#pragma unroll
        for (int j = 0; j < 8; j++) {
            const int m = __shfl_sync(FULL, myidx, bt * 8 + j);
            if (m != curm) {                          // warp-uniform
                flush_half(sWf, racc, fcnt, (b << 9) + curm, lane, half);
                racc[0] = racc[1] = 0ull;
                fcnt = 0.0f;
                curm = m;
            }
            racc[0] = add2(racc[0], x[bt][j].x);
            racc[1] = add2(racc[1], x[bt][j].y);
            fcnt += 1.0f;
        }
    }
    flush_half(sWf, racc, fcnt, (b << 9) + curm, lane, half);
}

// ---------------------------------------------------------------------------
// Kernel C: finalize, thread-per-ELEMENT (65536 threads, 256 blocks):
//   out[t] = bc[k] + pe[vowel][k] + sum[t] * (cnt>0 ? 1/cnt : 0)
// Each thread then zeroes exactly the sum slot it read (and k==0 zeroes cnt)
// so the accumulators are ready for the next graph replay.
// ---------------------------------------------------------------------------
__global__ __launch_bounds__(256) void final_kernel(
    const int* __restrict__ vowels,       // [B, M]
    float* __restrict__ out)              // [B, M, 8]
{
    const int t = blockIdx.x * blockDim.x + threadIdx.x;   // 0..65535
    const int k = t & 7;
    const int row = t >> 3;

    const int v = __ldg(vowels + row);
    const float cnt = g_scr[OFF_CNT + row];
    const float sum = g_scr[OFF_SUM + t];
    const float inv = (cnt > 0.0f) ? (1.0f / cnt) : 0.0f;

    out[t] = g_scr[OFF_BC + k] + g_scr[OFF_PE + v * OUTN + k] + sum * inv;

    // restore zero-invariant for next replay
    g_scr[OFF_SUM + t] = 0.0f;
    if (k == 0) g_scr[OFF_CNT + row] = 0.0f;
}

// ---------------------------------------------------------------------------
// launch: tiny memset (first-node cost absorber) + fold + proj(+pe) + final
// ---------------------------------------------------------------------------
extern "C" void kernel_launch(void* const* d_in, const int* in_sizes, int n_in,
                              void* d_out, int out_size)
{
    const int*   vowels     = (const int*)d_in[0];
    const float* features   = (const float*)d_in[1];
    const int*   mora_index = (const int*)d_in[2];
    const float* emb_table  = (const float*)d_in[3];
    const float* W_mora     = (const float*)d_in[4];
    const float* b_mora     = (const float*)d_in[5];
    // d_in[6] = W_frame, d_in[7] = b_frame: dead branch, unused
    const float* W_post     = (const float*)d_in[8];
    const float* b_post     = (const float*)d_in[9];
    float* out = (float*)d_out;

    // small leading memset: absorbs the per-replay first-node fixed cost.
    // Touches the weight region (overwritten by fold anyway); sum/cnt are
    // kept zero by final_kernel of the previous replay (BSS-zero initially).
    void* p_scr = nullptr;
    cudaGetSymbolAddress(&p_scr, g_scr);
    cudaMemsetAsync((char*)p_scr + OFF_WF * sizeof(float), 0,
                    (OFF_PE - OFF_WF) * sizeof(float));

    fold_kernel<<<41, 256>>>(W_mora, b_mora, W_post, b_post);
    proj_kernel<<<NPB + 2, 256>>>(features, mora_index, emb_table);
    final_kernel<<<(NSEG * OUTN) / 256, 256>>>(vowels, out);
}

// round 17
// speedup vs baseline: 1.1001x; 1.1001x over previous
#include <cuda_runtime.h>
#include <cuda_bf16.h>

typedef unsigned long long ull;

// Problem shapes (fixed)
#define BN 16
#define FN 4096
#define MN 512
#define DN 256
#define VEN 64
#define HN 512
#define OUTN 8
#define VN 50
#define INW 320          // VEN + DN
#define NSEG 8192        // BN * MN

#define NPB 1024         // proj main blocks: 8192 warps = 4096 chunks x 2 halves
#define FRPW 16          // frames per chunk (contiguous)

// ---------------------------------------------------------------------------
// One contiguous scratch array (single memset node zeroes [0, OFF_PE)).
//   sum   [NSEG*8]  @ 0        cnt [NSEG] @ 65536
//   Wf    [2048]    @ 73728    k-major ull view: ull[k*128+jp] = (Wc[64+2jp][k], Wc[64+2jp+1][k])
//   WcEmb [512]     @ 75776    bc [8] @ 76288    pe [400] @ 76296
// ---------------------------------------------------------------------------
#define OFF_SUM   0
#define OFF_CNT   65536
#define OFF_WF    73728
#define OFF_WCEMB 75776
#define OFF_BC    76288
#define OFF_PE    76296
#define SCR_TOTAL 76704

__device__ __align__(16) float g_scr[SCR_TOTAL];

__device__ __forceinline__ ull fma2(ull a, ull b, ull c) {
    ull d;
    asm("fma.rn.f32x2 %0, %1, %2, %3;" : "=l"(d) : "l"(a), "l"(b), "l"(c));
    return d;
}
__device__ __forceinline__ ull add2(ull a, ull b) {
    ull d;
    asm("add.rn.f32x2 %0, %1, %2;" : "=l"(d) : "l"(a), "l"(b));
    return d;
}

// ---------------------------------------------------------------------------
// Transposed warp reduction: v[0..7] per lane (k partials) -> each lane
// returns the full warp sum for k = lane & 7. 9 shuffles.
// ---------------------------------------------------------------------------
__device__ __forceinline__ float warp_reduce_k(const float v[8], int lane) {
    const unsigned FULL = 0xFFFFFFFFu;
    float nv[4];
    const int b0 = lane & 1;
#pragma unroll
    for (int i = 0; i < 4; i++) {
        float keep = b0 ? v[2 * i + 1] : v[2 * i];
        float send = b0 ? v[2 * i]     : v[2 * i + 1];
        nv[i] = keep + __shfl_xor_sync(FULL, send, 1);
    }
    const int b1 = (lane >> 1) & 1;
    float mv[2];
#pragma unroll
    for (int i = 0; i < 2; i++) {
        float keep = b1 ? nv[2 * i + 1] : nv[2 * i];
        float send = b1 ? nv[2 * i]     : nv[2 * i + 1];
        mv[i] = keep + __shfl_xor_sync(FULL, send, 2);
    }
    const int b2 = (lane >> 2) & 1;
    float keep = b2 ? mv[1] : mv[0];
    float send = b2 ? mv[0] : mv[1];
    float s = keep + __shfl_xor_sync(FULL, send, 4);
    s += __shfl_xor_sync(FULL, s, 8);
    s += __shfl_xor_sync(FULL, s, 16);
    return s;   // k = lane & 7
}

// ---------------------------------------------------------------------------
// Kernel A: fold Wc = W_mora @ W_post + bc. Warp-per-(row, H-half): 642 warps.
// No smem, no barrier; W_post read direct (L2-hot); atomicAdd into zeroed scr.
// (R15 measured best: 6.46us.)
// ---------------------------------------------------------------------------
__global__ __launch_bounds__(256) void fold_kernel(
    const float* __restrict__ W_mora,   // [320, 512]
    const float* __restrict__ b_mora,   // [512]
    const float* __restrict__ W_post,   // [512, 8]
    const float* __restrict__ b_post)   // [8]
{
    const int tid = threadIdx.x;
    const int lane = tid & 31;
    const int w = blockIdx.x * 8 + (tid >> 5);   // 0..647
    const int i = w >> 1;                        // row 0..323
    const int half = w & 1;
    if (i > INW) return;

    const float* src = (i < INW) ? (W_mora + (size_t)i * HN) : b_mora;

    float acc[8];
#pragma unroll
    for (int k = 0; k < 8; k++) acc[k] = 0.0f;

#pragma unroll
    for (int j = 0; j < 8; j++) {
        const int h = half * 256 + 32 * j + lane;
        const float a = src[h];
        const float4* wp = (const float4*)(W_post + h * OUTN);
        float4 p0 = wp[0], p1 = wp[1];
        acc[0] += a * p0.x; acc[1] += a * p0.y; acc[2] += a * p0.z; acc[3] += a * p0.w;
        acc[4] += a * p1.x; acc[5] += a * p1.y; acc[6] += a * p1.z; acc[7] += a * p1.w;
    }

    float s = warp_reduce_k(acc, lane);
    if (lane < 8) {
        const int k = lane;
        if (i < VEN) {
            atomicAdd(g_scr + OFF_WCEMB + i * OUTN + k, s);
        } else if (i < INW) {
            const int j = i - VEN;
            atomicAdd(g_scr + OFF_WF + (k * 128 + (j >> 1)) * 2 + (j & 1), s);
        } else {
            atomicAdd(g_scr + OFF_BC + k, s + (half == 0 ? b_post[k] : 0.0f));
        }
    }
}

// ---------------------------------------------------------------------------
// Flush (half-frame): project this warp's 4-per-lane run-sum (2 f32x2,
// dims [half*128, half*128+128)) with its half of the smem weights,
// transposed reduce, atomic scatter. cnt added by half 0 only.
// ---------------------------------------------------------------------------
__device__ __noinline__ void flush_half(const ull* __restrict__ sWf,
                                        const ull* __restrict__ racc,
                                        float fcnt, int seg, int lane, int half) {
    const int jp = half * 64 + 2 * lane;
    float v[8];
#pragma unroll
    for (int k = 0; k < 8; k++) {
        ulonglong2 wa = *(const ulonglong2*)(sWf + k * 128 + jp);
        ull t = fma2(racc[0], wa.x, fma2(racc[1], wa.y, 0ull));
        float lo = __int_as_float((int)(t & 0xFFFFFFFFull));
        float hi = __int_as_float((int)(t >> 32));
        v[k] = lo + hi;
    }
    float s = warp_reduce_k(v, lane);
    if (lane < 8) atomicAdd(g_scr + OFF_SUM + seg * OUTN + lane, s);
    else if (lane == 8 && half == 0) atomicAdd(g_scr + OFF_CNT + seg, fcnt);
}

// ---------------------------------------------------------------------------
// Kernel B: warp pair per 16-frame chunk (half 0: dims 0-127, half 1: 128-255).
// 1 LDG.128 per frame per lane; 8-frame batches, 2-deep software pipeline.
// Extra blocks compute pe.  (R15 winner, unchanged.)
// ---------------------------------------------------------------------------
__global__ __launch_bounds__(256) void proj_kernel(
    const float* __restrict__ features,   // [B, F, D]
    const int* __restrict__ mora_index,   // [B, F]
    const float* __restrict__ emb_table)  // [V, VE]
{
    const unsigned FULL = 0xFFFFFFFFu;

    if (blockIdx.x >= NPB) {
        // per-vowel embedding projection: pe[v][k] = emb[v] . WcEmb[:,k]
        const int gt = (blockIdx.x - NPB) * 256 + threadIdx.x;  // 2 blocks >= 400
        if (gt < VN * OUTN) {
            const int v = gt >> 3, k = gt & 7;
            const float* e = emb_table + v * VEN;
            float s = 0.0f;
#pragma unroll 8
            for (int j = 0; j < VEN; j++) s += e[j] * g_scr[OFF_WCEMB + j * OUTN + k];
            g_scr[OFF_PE + gt] = s;
        }
        return;
    }

    __shared__ __align__(16) ull sWf[128 * 8];   // 8 KB, k-major
    const int tid = threadIdx.x;
    for (int j = tid; j < 128 * 8 / 2; j += 256)
        ((ulonglong2*)sWf)[j] = ((const ulonglong2*)(g_scr + OFF_WF))[j];
    __syncthreads();

    const int lane = tid & 31;
    const int gw = (blockIdx.x * 256 + tid) >> 5;   // 0..8191
    const int chunk = gw >> 1;                      // 0..4095
    const int half = gw & 1;                        // dim half
    const int base = chunk * FRPW;                  // 16 contiguous frames
    const int b = base >> 12;                       // / FN

    // preload the 16 mora indices for this chunk (one coalesced LDG)
    const int myidx = mora_index[base + (lane & 15)];

    ull racc[2];
    racc[0] = racc[1] = 0ull;
    float fcnt = 0.0f;
    int curm = __shfl_sync(FULL, myidx, 0);

    // lane covers dims [half*128 + 4*lane, +4): one ulonglong2 per frame
    const ulonglong2* fr =
        (const ulonglong2*)(features + (size_t)base * DN + half * 128);

    // 2-deep software pipeline over 2 batches of 8 frames
    ulonglong2 x[2][8];
#pragma unroll
    for (int j = 0; j < 8; j++) x[0][j] = fr[j * 64 + lane];

#pragma unroll
    for (int bt = 0; bt < 2; bt++) {
        if (bt == 0) {
            // issue batch 1's 8 LDG.128 before consuming batch 0
#pragma unroll
            for (int j = 0; j < 8; j++) x[1][j] = fr[(8 + j) * 64 + lane];
        }
#pragma unroll
        for (int j = 0; j < 8; j++) {
            const int m = __shfl_sync(FULL, myidx, bt * 8 + j);
            if (m != curm) {                          // warp-uniform
                flush_half(sWf, racc, fcnt, (b << 9) + curm, lane, half);
                racc[0] = racc[1] = 0ull;
                fcnt = 0.0f;
                curm = m;
            }
            racc[0] = add2(racc[0], x[bt][j].x);
            racc[1] = add2(racc[1], x[bt][j].y);
            fcnt += 1.0f;
        }
    }
    flush_half(sWf, racc, fcnt, (b << 9) + curm, lane, half);
}

// ---------------------------------------------------------------------------
// Kernel C: finalize, thread-per-ELEMENT (65536 threads, 256 blocks):
//   out[t] = bc[k] + pe[vowel][k] + sum[t] * (cnt>0 ? 1/cnt : 0)
// ---------------------------------------------------------------------------
__global__ __launch_bounds__(256) void final_kernel(
    const int* __restrict__ vowels,       // [B, M]
    float* __restrict__ out)              // [B, M, 8]
{
    const int t = blockIdx.x * blockDim.x + threadIdx.x;   // 0..65535
    const int k = t & 7;
    const int row = t >> 3;

    const int v = __ldg(vowels + row);
    const float cnt = g_scr[OFF_CNT + row];
    const float sum = g_scr[OFF_SUM + t];
    const float inv = (cnt > 0.0f) ? (1.0f / cnt) : 0.0f;

    out[t] = g_scr[OFF_BC + k] + g_scr[OFF_PE + v * OUTN + k] + sum * inv;
}

// ---------------------------------------------------------------------------
// launch: memset (full zero, first-node cost absorber) + fold + proj(+pe) + final
// ---------------------------------------------------------------------------
extern "C" void kernel_launch(void* const* d_in, const int* in_sizes, int n_in,
                              void* d_out, int out_size)
{
    const int*   vowels     = (const int*)d_in[0];
    const float* features   = (const float*)d_in[1];
    const int*   mora_index = (const int*)d_in[2];
    const float* emb_table  = (const float*)d_in[3];
    const float* W_mora     = (const float*)d_in[4];
    const float* b_mora     = (const float*)d_in[5];
    // d_in[6] = W_frame, d_in[7] = b_frame: dead branch, unused
    const float* W_post     = (const float*)d_in[8];
    const float* b_post     = (const float*)d_in[9];
    float* out = (float*)d_out;

    // single memset node zeroes sum/cnt/Wf/WcEmb/bc (fold uses atomicAdd)
    void* p_scr = nullptr;
    cudaGetSymbolAddress(&p_scr, g_scr);
    cudaMemsetAsync(p_scr, 0, OFF_PE * sizeof(float));

    fold_kernel<<<81, 256>>>(W_mora, b_mora, W_post, b_post);
    proj_kernel<<<NPB + 2, 256>>>(features, mora_index, emb_table);
    final_kernel<<<(NSEG * OUTN) / 256, 256>>>(vowels, out);
}